// round 14
// baseline (speedup 1.0000x reference)
#include <cuda_runtime.h>
#include <cstdint>

// ---------------------------------------------------------------------------
// QMatMul: out[b,h] = A[b,h](2048x64) @ B[b,h](64x2048), fp32 via tf32
// mma.sync (harness target is sm_103 non-'a'; tcgen05 unavailable).
// Scales cancel mathematically: (A/sA)@(B/sB)*sA*sB == A@B. Only the trailing
// scalar output element needs sA*sB.
//
// R13 = R12 (298.8us) +
//   (1) A stored k-permuted (pi(j)=2(j&3)+(j>>2), stride 72) so each A
//       fragment pair (k+r, k+r+4) is one conflict-free LDS.64 -> A frag
//       LDS instruction count halves.
//   (2) scale tail folded into the gemm kernel (CTA 0) -> removes the
//       serialized 1-block tail launch (~3.8us of whole-GPU idle).
// ---------------------------------------------------------------------------

static constexpr int AS_STRIDE = 72;    // k-permuted; LDS.64 8B-bank = 4q+r, conflict-free
static constexpr int BS_STRIDE = 136;   // 128 + 8 (stride%32==8: b-frags conflict-free)
static constexpr int AS_FLOATS = 128 * AS_STRIDE;   // 9216
static constexpr int BS_FLOATS = 64 * BS_STRIDE;    // 8704 per stage
static constexpr uint32_t SMEM_BYTES = (AS_FLOATS + 2 * BS_FLOATS) * 4;  // 106496

static __device__ __forceinline__ uint32_t f2tf32(float x) {
    uint32_t r;
    asm("cvt.rna.tf32.f32 %0, %1;" : "=r"(r) : "f"(x));
    return r;
}

static __device__ __forceinline__ uint32_t smem_u32(const void* p) {
    uint32_t a;
    asm("{ .reg .u64 t; cvta.to.shared.u64 t, %1; cvt.u32.u64 %0, t; }"
        : "=r"(a) : "l"(p));
    return a;
}

static __device__ __forceinline__ void cp_async16(uint32_t dst_smem, const void* src) {
    asm volatile("cp.async.cg.shared.global [%0], [%1], 16;"
                 :: "r"(dst_smem), "l"(src) : "memory");
}

static __device__ __forceinline__ void mma_tf32(
    float& c0, float& c1, float& c2, float& c3,
    uint32_t a0, uint32_t a1, uint32_t a2, uint32_t a3,
    uint32_t b0, uint32_t b1)
{
    asm volatile(
        "mma.sync.aligned.m16n8k8.row.col.f32.tf32.tf32.f32 "
        "{%0,%1,%2,%3}, {%4,%5,%6,%7}, {%8,%9}, {%0,%1,%2,%3};"
        : "+f"(c0), "+f"(c1), "+f"(c2), "+f"(c3)
        : "r"(a0), "r"(a1), "r"(a2), "r"(a3), "r"(b0), "r"(b1));
}

__global__ void __launch_bounds__(256, 2)
qmm_tf32_kernel(const float* __restrict__ A,
                const float* __restrict__ B,
                const float* __restrict__ sA,
                const float* __restrict__ sB,
                float* __restrict__ out,
                long long out_size)
{
    extern __shared__ __align__(128) float smem[];
    float* As  = smem;                         // [128][72], tf32(rna), k-permuted
    float* Bs0 = smem + AS_FLOATS;             // [64][136], raw fp32
    float* Bs1 = Bs0 + BS_FLOATS;

    const int tid = threadIdx.x;
    const int wid = tid >> 5;
    const int lid = tid & 31;
    const int q = lid >> 2;        // 0..7
    const int r = lid & 3;         // 0..3

    const int n_group = blockIdx.x;  // 0..1  (8 n-tiles of 128 cols each)
    const int m_tile  = blockIdx.y;  // 0..15 (128 rows)
    const int bz      = blockIdx.z;  // 0..63

    // Folded scale-tail: CTA (0,0,0) fills out[NMAT..out_size) with sA*sB.
    const long long NMAT = 268435456LL;  // 4*16*2048*2048
    if (n_group == 0 && m_tile == 0 && bz == 0) {
        float s = sA[0] * sB[0];
        for (long long i = NMAT + tid; i < out_size; i += 256)
            out[i] = s;
    }

    const size_t batch_in = (size_t)bz * (2048 * 64);
    const float* Ag = A + batch_in + (size_t)m_tile * (128 * 64);
    const float* Bg = B + batch_in + (size_t)n_group * 1024;  // col base

    // ---- Prologue: kick off B tile 0 cp.async, then load+convert A --------
    {
        #pragma unroll
        for (int it = 0; it < 8; it++) {
            int i  = tid + it * 256;       // 0..2047
            int k  = i >> 5;               // k row 0..63
            int n4 = i & 31;               // 16B chunk along N
            uint32_t dst = smem_u32(Bs0 + k * BS_STRIDE + n4 * 4);
            cp_async16(dst, Bg + (size_t)k * 2048 + n4 * 4);
        }
        asm volatile("cp.async.commit_group;" ::: "memory");

        // A with k-permutation pi(j) = 2*(j&3) + (j>>2) within each 8-block.
        // A float4 chunk c4 covers k = 4*c4..4*c4+3: even c4 -> j=0..3 ->
        // positions k0+{0,2,4,6}; odd c4 -> j=4..7 -> k0+{1,3,5,7}.
        const float4* Af4 = (const float4*)Ag;
        #pragma unroll
        for (int it = 0; it < 8; it++) {
            int i = tid + it * 256;        // 0..2047
            float4 v = Af4[i];
            int row   = i >> 4;
            int c4    = i & 15;
            int kbase = (c4 >> 1) << 3;    // k0 = 8*(c4/2)
            int odd   = c4 & 1;
            uint32_t* dst = (uint32_t*)(As + row * AS_STRIDE + kbase + odd);
            dst[0] = f2tf32(v.x);
            dst[2] = f2tf32(v.y);
            dst[4] = f2tf32(v.z);
            dst[6] = f2tf32(v.w);
        }
        asm volatile("cp.async.wait_group 0;" ::: "memory");
    }
    __syncthreads();

    // ---- Warp tiling: 8 warps = 4(M) x 2(N); warp tile 32x64 ---------------
    const int warp_m = wid & 3;
    const int warp_n = wid >> 2;
    const int m0 = warp_m * 32;
    const int n0 = warp_n * 64;

    const float2* As2 = (const float2*)As;   // float2 stride = 36 per row

    float* Ogb = out + (size_t)bz * (2048 * 2048)
                     + (size_t)(m_tile * 128 + m0) * 2048
                     + n_group * 1024 + n0;

    float* Bcur = Bs0;
    float* Bnxt = Bs1;

    for (int t = 0; t < 8; t++) {
        // Prefetch next B tile (readers of Bnxt finished before the barrier
        // that ended the previous iteration).
        if (t < 7) {
            const float* Bgn = Bg + (t + 1) * 128;
            #pragma unroll
            for (int it = 0; it < 8; it++) {
                int i  = tid + it * 256;
                int k  = i >> 5;
                int n4 = i & 31;
                uint32_t dst = smem_u32(Bnxt + k * BS_STRIDE + n4 * 4);
                cp_async16(dst, Bgn + (size_t)k * 2048 + n4 * 4);
            }
            asm volatile("cp.async.commit_group;" ::: "memory");
        }

        float acc[2][8][4];
        #pragma unroll
        for (int mt = 0; mt < 2; mt++)
            #pragma unroll
            for (int nt = 0; nt < 8; nt++)
                #pragma unroll
                for (int e = 0; e < 4; e++) acc[mt][nt][e] = 0.0f;

        const uint32_t* Bsu = (const uint32_t*)Bcur;

        #pragma unroll
        for (int ks = 0; ks < 8; ks++) {
            const int k0 = ks * 8;

            // A fragments: one LDS.64 per (mt, row-half); permuted layout
            // puts (k0+r, k0+r+4) adjacent. 8B-bank = 4q+r: conflict-free.
            uint32_t af[2][4];
            #pragma unroll
            for (int mt = 0; mt < 2; mt++) {
                int rb0 = (m0 + mt * 16 + q) * 36 + (k0 >> 1) + r;
                float2 p0 = As2[rb0];
                float2 p1 = As2[rb0 + 8 * 36];
                af[mt][0] = __float_as_uint(p0.x);
                af[mt][1] = __float_as_uint(p1.x);
                af[mt][2] = __float_as_uint(p0.y);
                af[mt][3] = __float_as_uint(p1.y);
            }
            // B raw fp32 bits -> tf32 operand (HW truncates low mantissa).
            uint32_t bf[8][2];
            #pragma unroll
            for (int nt = 0; nt < 8; nt++) {
                int cb = (k0 + r) * BS_STRIDE + n0 + nt * 8 + q;
                bf[nt][0] = Bsu[cb];
                bf[nt][1] = Bsu[cb + 4 * BS_STRIDE];
            }
            #pragma unroll
            for (int mt = 0; mt < 2; mt++)
                #pragma unroll
                for (int nt = 0; nt < 8; nt++)
                    mma_tf32(acc[mt][nt][0], acc[mt][nt][1],
                             acc[mt][nt][2], acc[mt][nt][3],
                             af[mt][0], af[mt][1], af[mt][2], af[mt][3],
                             bf[nt][0], bf[nt][1]);
        }

        // Early barrier: wait for the prefetched tile + all warps' MMA reads
        // of Bcur, BEFORE the epilogue -> STG drain overlaps next tile.
        if (t < 7) {
            asm volatile("cp.async.wait_group 0;" ::: "memory");
            __syncthreads();
            float* tmp = Bcur; Bcur = Bnxt; Bnxt = tmp;
        }

        // ---- Epilogue: plain STG.64; full 32B sector coverage --------------
        float* Og = Ogb + (size_t)t * 128;
        #pragma unroll
        for (int mt = 0; mt < 2; mt++) {
            #pragma unroll
            for (int nt = 0; nt < 8; nt++) {
                int row0 = mt * 16 + q;
                int col  = nt * 8 + 2 * r;
                *(float2*)(Og + (size_t)row0 * 2048 + col) =
                    make_float2(acc[mt][nt][0], acc[mt][nt][1]);
                *(float2*)(Og + (size_t)(row0 + 8) * 2048 + col) =
                    make_float2(acc[mt][nt][2], acc[mt][nt][3]);
            }
        }
    }
}

extern "C" void kernel_launch(void* const* d_in, const int* in_sizes, int n_in,
                              void* d_out, int out_size)
{
    (void)in_sizes; (void)n_in;
    const float* A  = (const float*)d_in[0];
    const float* sA = (const float*)d_in[1];
    const float* B  = (const float*)d_in[2];
    const float* sB = (const float*)d_in[3];
    float* out = (float*)d_out;

    static bool attr_set = false;
    if (!attr_set) {
        cudaFuncSetAttribute(qmm_tf32_kernel,
                             cudaFuncAttributeMaxDynamicSharedMemorySize,
                             SMEM_BYTES);
        attr_set = true;
    }

    dim3 grid(2, 16, 64);  // (n_groups of 8 tiles, m_tiles, batch*heads)
    qmm_tf32_kernel<<<grid, 256, SMEM_BYTES>>>(A, B, sA, sB, out,
                                               (long long)out_size);
}

// round 15
// speedup vs baseline: 1.0800x; 1.0800x over previous
#include <cuda_runtime.h>
#include <cstdint>

// ---------------------------------------------------------------------------
// QMatMul: out[b,h] = A[b,h](2048x64) @ B[b,h](64x2048), fp32 via tf32
// mma.sync (harness target is sm_103 non-'a'; tcgen05 unavailable).
// Scales cancel mathematically: (A/sA)@(B/sB)*sA*sB == A@B. Only the trailing
// scalar output element needs sA*sB.
//
// R15 = exact R12 kernel (298.8us: cp.async double-buffered 8-N-tile walk,
// A cvt.rna in smem, B raw->tf32 HW truncation, early barrier) + the folded
// scale-tail from R13 (removes the serialized 1-block tail launch). The R13
// A-layout change is fully reverted (it regressed: +fma/+alu/+issue from
// float2 unpack and index math at the 128-reg cap).
// ---------------------------------------------------------------------------

static constexpr int AS_STRIDE = 68;    // 64 + 4  (stride%32==4: a-frags conflict-free)
static constexpr int BS_STRIDE = 136;   // 128 + 8 (stride%32==8: b-frags conflict-free)
static constexpr int AS_FLOATS = 128 * AS_STRIDE;   // 8704
static constexpr int BS_FLOATS = 64 * BS_STRIDE;    // 8704 per stage
static constexpr uint32_t SMEM_BYTES = (AS_FLOATS + 2 * BS_FLOATS) * 4;  // 104448

static __device__ __forceinline__ uint32_t f2tf32(float x) {
    uint32_t r;
    asm("cvt.rna.tf32.f32 %0, %1;" : "=r"(r) : "f"(x));
    return r;
}

static __device__ __forceinline__ uint32_t smem_u32(const void* p) {
    uint32_t a;
    asm("{ .reg .u64 t; cvta.to.shared.u64 t, %1; cvt.u32.u64 %0, t; }"
        : "=r"(a) : "l"(p));
    return a;
}

static __device__ __forceinline__ void cp_async16(uint32_t dst_smem, const void* src) {
    asm volatile("cp.async.cg.shared.global [%0], [%1], 16;"
                 :: "r"(dst_smem), "l"(src) : "memory");
}

static __device__ __forceinline__ void mma_tf32(
    float& c0, float& c1, float& c2, float& c3,
    uint32_t a0, uint32_t a1, uint32_t a2, uint32_t a3,
    uint32_t b0, uint32_t b1)
{
    asm volatile(
        "mma.sync.aligned.m16n8k8.row.col.f32.tf32.tf32.f32 "
        "{%0,%1,%2,%3}, {%4,%5,%6,%7}, {%8,%9}, {%0,%1,%2,%3};"
        : "+f"(c0), "+f"(c1), "+f"(c2), "+f"(c3)
        : "r"(a0), "r"(a1), "r"(a2), "r"(a3), "r"(b0), "r"(b1));
}

__global__ void __launch_bounds__(256, 2)
qmm_tf32_kernel(const float* __restrict__ A,
                const float* __restrict__ B,
                const float* __restrict__ sA,
                const float* __restrict__ sB,
                float* __restrict__ out,
                long long out_size)
{
    extern __shared__ __align__(128) float smem[];
    float* As  = smem;                         // [128][AS_STRIDE], tf32-rounded (rna)
    float* Bs0 = smem + AS_FLOATS;             // [64][BS_STRIDE], raw fp32
    float* Bs1 = Bs0 + BS_FLOATS;

    const int tid = threadIdx.x;
    const int wid = tid >> 5;
    const int lid = tid & 31;
    const int q = lid >> 2;        // 0..7
    const int r = lid & 3;         // 0..3

    const int n_group = blockIdx.x;  // 0..1  (8 n-tiles of 128 cols each)
    const int m_tile  = blockIdx.y;  // 0..15 (128 rows)
    const int bz      = blockIdx.z;  // 0..63

    // Folded scale-tail: CTA (0,0,0) fills out[NMAT..out_size) with sA*sB.
    const long long NMAT = 268435456LL;  // 4*16*2048*2048
    if (n_group == 0 && m_tile == 0 && bz == 0) {
        float s = sA[0] * sB[0];
        for (long long i = NMAT + tid; i < out_size; i += 256)
            out[i] = s;
    }

    const size_t batch_in = (size_t)bz * (2048 * 64);
    const float* Ag = A + batch_in + (size_t)m_tile * (128 * 64);
    const float* Bg = B + batch_in + (size_t)n_group * 1024;  // col base

    // ---- Prologue: kick off B tile 0 cp.async, then load+convert A --------
    {
        #pragma unroll
        for (int it = 0; it < 8; it++) {
            int i  = tid + it * 256;       // 0..2047
            int k  = i >> 5;               // k row 0..63
            int n4 = i & 31;               // 16B chunk along N
            uint32_t dst = smem_u32(Bs0 + k * BS_STRIDE + n4 * 4);
            cp_async16(dst, Bg + (size_t)k * 2048 + n4 * 4);
        }
        asm volatile("cp.async.commit_group;" ::: "memory");

        const float4* Af4 = (const float4*)Ag;
        #pragma unroll
        for (int it = 0; it < 8; it++) {
            int i = tid + it * 256;        // 0..2047
            float4 v = Af4[i];
            int row = i >> 4;
            int c4  = i & 15;
            uint32_t* dst = (uint32_t*)(As + row * AS_STRIDE + c4 * 4);
            dst[0] = f2tf32(v.x); dst[1] = f2tf32(v.y);
            dst[2] = f2tf32(v.z); dst[3] = f2tf32(v.w);
        }
        asm volatile("cp.async.wait_group 0;" ::: "memory");
    }
    __syncthreads();

    // ---- Warp tiling: 8 warps = 4(M) x 2(N); warp tile 32x64 ---------------
    const int warp_m = wid & 3;
    const int warp_n = wid >> 2;
    const int m0 = warp_m * 32;
    const int n0 = warp_n * 64;

    const uint32_t* Asu = (const uint32_t*)As;

    float* Ogb = out + (size_t)bz * (2048 * 2048)
                     + (size_t)(m_tile * 128 + m0) * 2048
                     + n_group * 1024 + n0;

    float* Bcur = Bs0;
    float* Bnxt = Bs1;

    for (int t = 0; t < 8; t++) {
        // Prefetch next B tile (readers of Bnxt finished before the barrier
        // that ended the previous iteration).
        if (t < 7) {
            const float* Bgn = Bg + (t + 1) * 128;
            #pragma unroll
            for (int it = 0; it < 8; it++) {
                int i  = tid + it * 256;
                int k  = i >> 5;
                int n4 = i & 31;
                uint32_t dst = smem_u32(Bnxt + k * BS_STRIDE + n4 * 4);
                cp_async16(dst, Bgn + (size_t)k * 2048 + n4 * 4);
            }
            asm volatile("cp.async.commit_group;" ::: "memory");
        }

        float acc[2][8][4];
        #pragma unroll
        for (int mt = 0; mt < 2; mt++)
            #pragma unroll
            for (int nt = 0; nt < 8; nt++)
                #pragma unroll
                for (int e = 0; e < 4; e++) acc[mt][nt][e] = 0.0f;

        const uint32_t* Bsu = (const uint32_t*)Bcur;

        #pragma unroll
        for (int ks = 0; ks < 8; ks++) {
            const int k0 = ks * 8;

            uint32_t af[2][4];
            #pragma unroll
            for (int mt = 0; mt < 2; mt++) {
                int rb = (m0 + mt * 16 + q) * AS_STRIDE + k0 + r;
                af[mt][0] = Asu[rb];
                af[mt][1] = Asu[rb + 8 * AS_STRIDE];
                af[mt][2] = Asu[rb + 4];
                af[mt][3] = Asu[rb + 8 * AS_STRIDE + 4];
            }
            // B raw fp32 bits -> tf32 operand (HW truncates low mantissa).
            uint32_t bf[8][2];
            #pragma unroll
            for (int nt = 0; nt < 8; nt++) {
                int cb = (k0 + r) * BS_STRIDE + n0 + nt * 8 + q;
                bf[nt][0] = Bsu[cb];
                bf[nt][1] = Bsu[cb + 4 * BS_STRIDE];
            }
            #pragma unroll
            for (int mt = 0; mt < 2; mt++)
                #pragma unroll
                for (int nt = 0; nt < 8; nt++)
                    mma_tf32(acc[mt][nt][0], acc[mt][nt][1],
                             acc[mt][nt][2], acc[mt][nt][3],
                             af[mt][0], af[mt][1], af[mt][2], af[mt][3],
                             bf[nt][0], bf[nt][1]);
        }

        // Early barrier: wait for the prefetched tile + all warps' MMA reads
        // of Bcur, BEFORE the epilogue -> STG drain overlaps next tile.
        if (t < 7) {
            asm volatile("cp.async.wait_group 0;" ::: "memory");
            __syncthreads();
            float* tmp = Bcur; Bcur = Bnxt; Bnxt = tmp;
        }

        // ---- Epilogue: plain STG.64; full 32B sector coverage --------------
        float* Og = Ogb + (size_t)t * 128;
        #pragma unroll
        for (int mt = 0; mt < 2; mt++) {
            #pragma unroll
            for (int nt = 0; nt < 8; nt++) {
                int row0 = mt * 16 + q;
                int col  = nt * 8 + 2 * r;
                *(float2*)(Og + (size_t)row0 * 2048 + col) =
                    make_float2(acc[mt][nt][0], acc[mt][nt][1]);
                *(float2*)(Og + (size_t)(row0 + 8) * 2048 + col) =
                    make_float2(acc[mt][nt][2], acc[mt][nt][3]);
            }
        }
    }
}

extern "C" void kernel_launch(void* const* d_in, const int* in_sizes, int n_in,
                              void* d_out, int out_size)
{
    (void)in_sizes; (void)n_in;
    const float* A  = (const float*)d_in[0];
    const float* sA = (const float*)d_in[1];
    const float* B  = (const float*)d_in[2];
    const float* sB = (const float*)d_in[3];
    float* out = (float*)d_out;

    static bool attr_set = false;
    if (!attr_set) {
        cudaFuncSetAttribute(qmm_tf32_kernel,
                             cudaFuncAttributeMaxDynamicSharedMemorySize,
                             SMEM_BYTES);
        attr_set = true;
    }

    dim3 grid(2, 16, 64);  // (n_groups of 8 tiles, m_tiles, batch*heads)
    qmm_tf32_kernel<<<grid, 256, SMEM_BYTES>>>(A, B, sA, sB, out,
                                               (long long)out_size);
}

// round 17
// speedup vs baseline: 1.0868x; 1.0063x over previous
#include <cuda_runtime.h>
#include <cstdint>

// ---------------------------------------------------------------------------
// QMatMul: out[b,h] = A[b,h](2048x64) @ B[b,h](64x2048), fp32 via tf32
// mma.sync (harness target is sm_103 non-'a'; tcgen05 unavailable).
// Scales cancel mathematically: (A/sA)@(B/sB)*sA*sB == A@B. Only the trailing
// scalar output element needs sA*sB.
//
// R16 = R15 (295.0us) + ONE isolated change: epilogue stores use
// st.global.cs (evict-first streaming hint). The output is write-once /
// never-read; streaming stores let L2 retire the lines eagerly, shortening
// the write-back path that the DRAM model says is the binding resource
// (3.68 TB/s pure-write = ~92% of a ~4 TB/s write-only ceiling).
// ---------------------------------------------------------------------------

static constexpr int AS_STRIDE = 68;    // 64 + 4  (stride%32==4: a-frags conflict-free)
static constexpr int BS_STRIDE = 136;   // 128 + 8 (stride%32==8: b-frags conflict-free)
static constexpr int AS_FLOATS = 128 * AS_STRIDE;   // 8704
static constexpr int BS_FLOATS = 64 * BS_STRIDE;    // 8704 per stage
static constexpr uint32_t SMEM_BYTES = (AS_FLOATS + 2 * BS_FLOATS) * 4;  // 104448

static __device__ __forceinline__ uint32_t f2tf32(float x) {
    uint32_t r;
    asm("cvt.rna.tf32.f32 %0, %1;" : "=r"(r) : "f"(x));
    return r;
}

static __device__ __forceinline__ uint32_t smem_u32(const void* p) {
    uint32_t a;
    asm("{ .reg .u64 t; cvta.to.shared.u64 t, %1; cvt.u32.u64 %0, t; }"
        : "=r"(a) : "l"(p));
    return a;
}

static __device__ __forceinline__ void cp_async16(uint32_t dst_smem, const void* src) {
    asm volatile("cp.async.cg.shared.global [%0], [%1], 16;"
                 :: "r"(dst_smem), "l"(src) : "memory");
}

static __device__ __forceinline__ void stcs2(float* p, float x, float y) {
    asm volatile("st.global.cs.v2.f32 [%0], {%1, %2};"
                 :: "l"(p), "f"(x), "f"(y) : "memory");
}

static __device__ __forceinline__ void mma_tf32(
    float& c0, float& c1, float& c2, float& c3,
    uint32_t a0, uint32_t a1, uint32_t a2, uint32_t a3,
    uint32_t b0, uint32_t b1)
{
    asm volatile(
        "mma.sync.aligned.m16n8k8.row.col.f32.tf32.tf32.f32 "
        "{%0,%1,%2,%3}, {%4,%5,%6,%7}, {%8,%9}, {%0,%1,%2,%3};"
        : "+f"(c0), "+f"(c1), "+f"(c2), "+f"(c3)
        : "r"(a0), "r"(a1), "r"(a2), "r"(a3), "r"(b0), "r"(b1));
}

__global__ void __launch_bounds__(256, 2)
qmm_tf32_kernel(const float* __restrict__ A,
                const float* __restrict__ B,
                const float* __restrict__ sA,
                const float* __restrict__ sB,
                float* __restrict__ out,
                long long out_size)
{
    extern __shared__ __align__(128) float smem[];
    float* As  = smem;                         // [128][AS_STRIDE], tf32-rounded (rna)
    float* Bs0 = smem + AS_FLOATS;             // [64][BS_STRIDE], raw fp32
    float* Bs1 = Bs0 + BS_FLOATS;

    const int tid = threadIdx.x;
    const int wid = tid >> 5;
    const int lid = tid & 31;
    const int q = lid >> 2;        // 0..7
    const int r = lid & 3;         // 0..3

    const int n_group = blockIdx.x;  // 0..1  (8 n-tiles of 128 cols each)
    const int m_tile  = blockIdx.y;  // 0..15 (128 rows)
    const int bz      = blockIdx.z;  // 0..63

    // Folded scale-tail: CTA (0,0,0) fills out[NMAT..out_size) with sA*sB.
    const long long NMAT = 268435456LL;  // 4*16*2048*2048
    if (n_group == 0 && m_tile == 0 && bz == 0) {
        float s = sA[0] * sB[0];
        for (long long i = NMAT + tid; i < out_size; i += 256)
            out[i] = s;
    }

    const size_t batch_in = (size_t)bz * (2048 * 64);
    const float* Ag = A + batch_in + (size_t)m_tile * (128 * 64);
    const float* Bg = B + batch_in + (size_t)n_group * 1024;  // col base

    // ---- Prologue: kick off B tile 0 cp.async, then load+convert A --------
    {
        #pragma unroll
        for (int it = 0; it < 8; it++) {
            int i  = tid + it * 256;       // 0..2047
            int k  = i >> 5;               // k row 0..63
            int n4 = i & 31;               // 16B chunk along N
            uint32_t dst = smem_u32(Bs0 + k * BS_STRIDE + n4 * 4);
            cp_async16(dst, Bg + (size_t)k * 2048 + n4 * 4);
        }
        asm volatile("cp.async.commit_group;" ::: "memory");

        const float4* Af4 = (const float4*)Ag;
        #pragma unroll
        for (int it = 0; it < 8; it++) {
            int i = tid + it * 256;        // 0..2047
            float4 v = Af4[i];
            int row = i >> 4;
            int c4  = i & 15;
            uint32_t* dst = (uint32_t*)(As + row * AS_STRIDE + c4 * 4);
            dst[0] = f2tf32(v.x); dst[1] = f2tf32(v.y);
            dst[2] = f2tf32(v.z); dst[3] = f2tf32(v.w);
        }
        asm volatile("cp.async.wait_group 0;" ::: "memory");
    }
    __syncthreads();

    // ---- Warp tiling: 8 warps = 4(M) x 2(N); warp tile 32x64 ---------------
    const int warp_m = wid & 3;
    const int warp_n = wid >> 2;
    const int m0 = warp_m * 32;
    const int n0 = warp_n * 64;

    const uint32_t* Asu = (const uint32_t*)As;

    float* Ogb = out + (size_t)bz * (2048 * 2048)
                     + (size_t)(m_tile * 128 + m0) * 2048
                     + n_group * 1024 + n0;

    float* Bcur = Bs0;
    float* Bnxt = Bs1;

    for (int t = 0; t < 8; t++) {
        // Prefetch next B tile (readers of Bnxt finished before the barrier
        // that ended the previous iteration).
        if (t < 7) {
            const float* Bgn = Bg + (t + 1) * 128;
            #pragma unroll
            for (int it = 0; it < 8; it++) {
                int i  = tid + it * 256;
                int k  = i >> 5;
                int n4 = i & 31;
                uint32_t dst = smem_u32(Bnxt + k * BS_STRIDE + n4 * 4);
                cp_async16(dst, Bgn + (size_t)k * 2048 + n4 * 4);
            }
            asm volatile("cp.async.commit_group;" ::: "memory");
        }

        float acc[2][8][4];
        #pragma unroll
        for (int mt = 0; mt < 2; mt++)
            #pragma unroll
            for (int nt = 0; nt < 8; nt++)
                #pragma unroll
                for (int e = 0; e < 4; e++) acc[mt][nt][e] = 0.0f;

        const uint32_t* Bsu = (const uint32_t*)Bcur;

        #pragma unroll
        for (int ks = 0; ks < 8; ks++) {
            const int k0 = ks * 8;

            uint32_t af[2][4];
            #pragma unroll
            for (int mt = 0; mt < 2; mt++) {
                int rb = (m0 + mt * 16 + q) * AS_STRIDE + k0 + r;
                af[mt][0] = Asu[rb];
                af[mt][1] = Asu[rb + 8 * AS_STRIDE];
                af[mt][2] = Asu[rb + 4];
                af[mt][3] = Asu[rb + 8 * AS_STRIDE + 4];
            }
            // B raw fp32 bits -> tf32 operand (HW truncates low mantissa).
            uint32_t bf[8][2];
            #pragma unroll
            for (int nt = 0; nt < 8; nt++) {
                int cb = (k0 + r) * BS_STRIDE + n0 + nt * 8 + q;
                bf[nt][0] = Bsu[cb];
                bf[nt][1] = Bsu[cb + 4 * BS_STRIDE];
            }
            #pragma unroll
            for (int mt = 0; mt < 2; mt++)
                #pragma unroll
                for (int nt = 0; nt < 8; nt++)
                    mma_tf32(acc[mt][nt][0], acc[mt][nt][1],
                             acc[mt][nt][2], acc[mt][nt][3],
                             af[mt][0], af[mt][1], af[mt][2], af[mt][3],
                             bf[nt][0], bf[nt][1]);
        }

        // Early barrier: wait for the prefetched tile + all warps' MMA reads
        // of Bcur, BEFORE the epilogue -> STG drain overlaps next tile.
        if (t < 7) {
            asm volatile("cp.async.wait_group 0;" ::: "memory");
            __syncthreads();
            float* tmp = Bcur; Bcur = Bnxt; Bnxt = tmp;
        }

        // ---- Epilogue: streaming st.global.cs.v2; full sector coverage ----
        float* Og = Ogb + (size_t)t * 128;
        #pragma unroll
        for (int mt = 0; mt < 2; mt++) {
            #pragma unroll
            for (int nt = 0; nt < 8; nt++) {
                int row0 = mt * 16 + q;
                int col  = nt * 8 + 2 * r;
                stcs2(Og + (size_t)row0 * 2048 + col,
                      acc[mt][nt][0], acc[mt][nt][1]);
                stcs2(Og + (size_t)(row0 + 8) * 2048 + col,
                      acc[mt][nt][2], acc[mt][nt][3]);
            }
        }
    }
}

extern "C" void kernel_launch(void* const* d_in, const int* in_sizes, int n_in,
                              void* d_out, int out_size)
{
    (void)in_sizes; (void)n_in;
    const float* A  = (const float*)d_in[0];
    const float* sA = (const float*)d_in[1];
    const float* B  = (const float*)d_in[2];
    const float* sB = (const float*)d_in[3];
    float* out = (float*)d_out;

    static bool attr_set = false;
    if (!attr_set) {
        cudaFuncSetAttribute(qmm_tf32_kernel,
                             cudaFuncAttributeMaxDynamicSharedMemorySize,
                             SMEM_BYTES);
        attr_set = true;
    }

    dim3 grid(2, 16, 64);  // (n_groups of 8 tiles, m_tiles, batch*heads)
    qmm_tf32_kernel<<<grid, 256, SMEM_BYTES>>>(A, B, sA, sB, out,
                                               (long long)out_size);
}